// round 12
// baseline (speedup 1.0000x reference)
#include <cuda_runtime.h>
#include <cstdint>

#define BATCH       64
#define SIZE        224
#define PIXELS      (SIZE*SIZE)        // 50176
#define DIM         40
#define NUM_CLASSES 10
#define WORDS       (PIXELS/32)        // 1568
#define NCHUNK      28                 // word chunks in main role
#define CW          (WORDS/NCHUNK)     // 56 words per chunk (exact)
#define QPITCH      57                 // gcd(57,32)=1 -> conflict-free strides
#define BPB         4                  // batches per main block
#define NQUAD       (BATCH/BPB)        // 16
#define PPB         128                // pixels per pack block
#define NBP         (PIXELS/PPB)       // 392 pack blocks (bids 0..391: wave-1)
#define NMAIN       (NCHUNK*NQUAD)     // 448 main blocks
#define NTOT        (NBP+NMAIN)        // 840 total; 6 blocks/SM x 148 = 888 >= 840

// Globals. g_A/g_C are atomic accumulators starting at 0 (load-time zeroed);
// the finisher block re-zeroes them each run -> invariant across graph replays.
__device__ uint32_t g_Q[DIM * WORDS];          // 251 KB packed pos signs
__device__ int      g_TotPart[NCHUNK * DIM];   // deterministic Tot partials
__device__ int      g_A[BATCH * DIM];          // AND-popc accumulators (atomic)
__device__ int      g_C[BATCH];                // mask-popc accumulators (atomic)
__device__ int      g_FlagP = 0;               // pack-done counter
__device__ int      g_FlagM = 0;               // main-done counter

// ---------------------------------------------------------------------------
// Single fused kernel.
// Pack role (bid < NBP): pos tile -> smem transpose -> ballots -> g_Q,
//   threadfence, arrive on g_FlagP. Never waits (no deadlock).
// Main role: (1) x-ballot into smem (overlaps pack DRAM), (2) spin FlagP,
//   (3) stage Q chunk, (4) AND+popc GEMM -> shared reduce -> ONE global
//   atomicAdd per (b,d), (5) fence + arrive FlagM. The last arriver is the
//   FINISHER: reduces Tot, computes exact integer epilogue + sign + classify,
//   writes out, then resets g_A/g_C/flags for the next replay.
//
// Exactness: pos/level are exactly {-1,+1}; NUM_LEVELS=2 -> idx=round(x) with
// half-to-even so level-1 <=> x>0.5 strictly. All sums to `enc` are exact
// integers (int atomics are associative -> deterministic, bit-exact).
// ---------------------------------------------------------------------------
__global__ void __launch_bounds__(320, 6)
fused_kernel(const float* __restrict__ x,
             const float* __restrict__ pos,
             const float* __restrict__ lvl,
             const float* __restrict__ cls,
             float* __restrict__ out) {
    const int tid  = threadIdx.x;
    const int lane = tid & 31;
    const int wid  = tid >> 5;                 // 10 warps

    if (blockIdx.x < NBP) {
        // ================= pack role =================
        __shared__ float tile[PPB * 41];       // 21 KB
        const int p0 = blockIdx.x * PPB;
        const int p  = tid / DIM;
        const int d  = tid - p * DIM;
        const float* __restrict__ src = pos + (size_t)(p0 + p) * DIM + d;
        float* dst = &tile[p * 41 + d];
        #pragma unroll
        for (int k = 0; k < PPB / 8; k++)      // 16 coalesced loads/thread
            dst[k * (8 * 41)] = src[k * (8 * DIM)];
        __syncthreads();

        #pragma unroll
        for (int k = 0; k < 4; k++) {          // warp packs 4 dims x 4 words
            int dd = wid * 4 + k;
            unsigned q0 = __ballot_sync(0xffffffffu, tile[lane * 41 + dd]        > 0.0f);
            unsigned q1 = __ballot_sync(0xffffffffu, tile[(32 + lane) * 41 + dd] > 0.0f);
            unsigned q2 = __ballot_sync(0xffffffffu, tile[(64 + lane) * 41 + dd] > 0.0f);
            unsigned q3 = __ballot_sync(0xffffffffu, tile[(96 + lane) * 41 + dd] > 0.0f);
            if (lane == 0)                     // p0/32 multiple of 4 -> 16B-aligned
                *reinterpret_cast<uint4*>(&g_Q[dd * WORDS + (p0 >> 5)]) =
                    make_uint4(q0, q1, q2, q3);
        }
        __threadfence();
        __syncthreads();
        if (tid == 0) atomicAdd(&g_FlagP, 1);
    } else {
        // ================= main role =================
        const int mb = blockIdx.x - NBP;
        const int c  = mb >> 4;                // chunk 0..27
        const int bq = mb & 15;
        const int b0 = bq * BPB;

        __shared__ uint32_t sQ[DIM * QPITCH];  // 9.1 KB
        __shared__ uint32_t sM[BPB][CW];       // 0.9 KB
        __shared__ int   sAcc[BPB][DIM];
        __shared__ int   sC[BPB];
        __shared__ int   sIsLast;
        __shared__ float encS[BATCH * DIM];    // 10.2 KB (finisher only)
        __shared__ int   sTotF[DIM];
        __shared__ int   sCB[BATCH];

        if (tid < DIM) {
            #pragma unroll
            for (int i = 0; i < BPB; i++) sAcc[i][tid] = 0;
        }
        if (tid < BPB) sC[tid] = 0;

        const int w0 = c * CW;
        int cc[BPB] = {0, 0, 0, 0};
        // Phase 1: x-ballot (no Q needed) — overlaps pack blocks' DRAM use.
        if (wid < 8) {
            const float* __restrict__ xb = x + (size_t)b0 * PIXELS + (size_t)w0 * 32;
            const int jbase = wid * (CW / 8);  // 7 words/warp
            #pragma unroll
            for (int jj = 0; jj < CW / 8; jj++) {
                int j = jbase + jj;
                #pragma unroll
                for (int i = 0; i < BPB; i++) {
                    float v = xb[(size_t)i * PIXELS + j * 32 + lane];
                    unsigned m = __ballot_sync(0xffffffffu, v > 0.5f);
                    cc[i] += __popc(m);
                    if (lane == 0) sM[i][j] = m;
                }
            }
        }

        // Phase 2: wait for pack completion (pack blocks are wave-1, no deadlock).
        if (tid == 0) {
            volatile int* fp = &g_FlagP;
            while (*fp != NBP) { }
        }
        __syncthreads();

        // Phase 3: stage Q chunk (uint4).
        for (int i = tid; i < DIM * (CW / 4); i += 320) {
            int d = i / (CW / 4), j4 = i - d * (CW / 4);
            uint4 v = *reinterpret_cast<const uint4*>(&g_Q[d * WORDS + w0 + j4 * 4]);
            uint32_t* q = &sQ[d * QPITCH + j4 * 4];
            q[0] = v.x; q[1] = v.y; q[2] = v.z; q[3] = v.w;
        }
        __syncthreads();

        // Phase 4: AND+popc GEMM, per-lane dim accumulators -> shared reduce.
        if (wid < 8) {
            const int jbase = wid * (CW / 8);
            int aLo[BPB] = {0, 0, 0, 0};
            int aHi[BPB] = {0, 0, 0, 0};
            #pragma unroll
            for (int jj = 0; jj < CW / 8; jj++) {
                int j = jbase + jj;
                uint32_t q0 = sQ[lane * QPITCH + j];            // dim = lane
                #pragma unroll
                for (int i = 0; i < BPB; i++) aLo[i] += __popc(sM[i][j] & q0);
                if (lane < 8) {
                    uint32_t q1 = sQ[(lane + 32) * QPITCH + j]; // dims 32..39
                    #pragma unroll
                    for (int i = 0; i < BPB; i++) aHi[i] += __popc(sM[i][j] & q1);
                }
            }
            #pragma unroll
            for (int i = 0; i < BPB; i++) {
                atomicAdd(&sAcc[i][lane], aLo[i]);
                if (lane < 8) atomicAdd(&sAcc[i][lane + 32], aHi[i]);
                if (lane == 0) atomicAdd(&sC[i], cc[i]);
            }
            if (bq == 0) {                     // Tot partials from resident sQ
                #pragma unroll
                for (int k = 0; k < DIM / 8; k++) {
                    int d = wid + 8 * k;
                    int t = 0;
                    for (int j = lane; j < CW; j += 32)
                        t += __popc(sQ[d * QPITCH + j]);
                    t = __reduce_add_sync(0xffffffffu, t);
                    if (lane == 0) g_TotPart[c * DIM + d] = t;
                }
            }
        }
        __syncthreads();

        // One global atomicAdd per (b,d): 28 adds/address across all blocks.
        if (tid < DIM) {
            #pragma unroll
            for (int i = 0; i < BPB; i++)
                atomicAdd(&g_A[(b0 + i) * DIM + tid], sAcc[i][tid]);
        }
        if (tid < BPB) atomicAdd(&g_C[b0 + tid], sC[tid]);

        __threadfence();
        __syncthreads();
        if (tid == 0) {
            int done = atomicAdd(&g_FlagM, 1);
            sIsLast = (done == NMAIN - 1);
        }
        __syncthreads();

        // ================= finisher =================
        if (sIsLast) {
            __threadfence();                   // acquire all main-block writes
            if (tid < DIM) {
                int t = 0;
                #pragma unroll
                for (int cc2 = 0; cc2 < NCHUNK; cc2++) t += g_TotPart[cc2 * DIM + tid];
                sTotF[tid] = t;
            }
            if (tid < BATCH) sCB[tid] = g_C[tid];
            __syncthreads();

            #pragma unroll
            for (int k = 0; k < (BATCH * DIM) / 320; k++) {   // 8 pairs/thread
                int p = k * 320 + tid;
                int b = p / DIM, d = p - b * DIM;
                int A   = 2 * g_A[p]    - sCB[b];
                int Tot = 2 * sTotF[d]  - PIXELS;
                float summed = lvl[d] * (float)(Tot - A) + lvl[DIM + d] * (float)A;
                encS[p] = (summed > 0.0f) ? 1.0f : -1.0f;
            }
            __syncthreads();

            #pragma unroll
            for (int k = 0; k < (BATCH * NUM_CLASSES) / 320; k++) {  // 2 outs/thread
                int t = k * 320 + tid;
                int b = t / NUM_CLASSES, cl = t - b * NUM_CLASSES;
                float acc = 0.0f;
                #pragma unroll
                for (int d = 0; d < DIM; d++) acc += encS[b * DIM + d] * cls[cl * DIM + d];
                out[t] = acc;
            }

            // Reset accumulators + flags for the next graph replay.
            #pragma unroll
            for (int k = 0; k < (BATCH * DIM) / 320; k++) g_A[k * 320 + tid] = 0;
            if (tid < BATCH) g_C[tid] = 0;
            if (tid == 0) { g_FlagP = 0; g_FlagM = 0; }
            __threadfence();
        }
    }
}

// ---------------------------------------------------------------------------
extern "C" void kernel_launch(void* const* d_in, const int* in_sizes, int n_in,
                              void* d_out, int out_size) {
    const float* x   = (const float*)d_in[0];   // [64, 224, 224]
    const float* pos = (const float*)d_in[1];   // [50176, 40]
    const float* lvl = (const float*)d_in[2];   // [2, 40]
    const float* cls = (const float*)d_in[3];   // [10, 40]
    float* out = (float*)d_out;                 // [64, 10]

    fused_kernel<<<NTOT, 320>>>(x, pos, lvl, cls, out);
}

// round 13
// speedup vs baseline: 1.0333x; 1.0333x over previous
#include <cuda_runtime.h>
#include <cstdint>

#define BATCH       64
#define SIZE        224
#define PIXELS      (SIZE*SIZE)        // 50176
#define DIM         40
#define NUM_CLASSES 10
#define WORDS       (PIXELS/32)        // 1568
#define NCHUNK      28                 // word chunks in main role
#define CW          (WORDS/NCHUNK)     // 56 words per chunk (exact)
#define QPITCH      57                 // gcd(57,32)=1 -> conflict-free strides
#define BPB         4                  // batches per main block
#define NQUAD       (BATCH/BPB)        // 16
#define PPB         128                // pixels per pack block
#define NBP         (PIXELS/PPB)       // 392 pack blocks (bids 0..391: wave-1)
#define NMAIN       (NCHUNK*NQUAD)     // 448 main blocks
#define NTOT        (NBP+NMAIN)        // 840 total; 6 blocks/SM x 148 = 888 >= 840

// Shared buffer sizes (bytes)
#define TILE_BYTES  (PPB*41*4)         // 20992 (pack tile)
#define SQ_BYTES    (DIM*QPITCH*4)     // 9120
#define SM_OFF      SQ_BYTES           // sM starts right after sQ (9120, 16-aligned)
#define SM_BYTES    (BPB*CW*4)         // 896
#define BUF_BYTES   TILE_BYTES         // 20992 >= max(pack, sQ+sM, encS)

// Globals. g_A/g_C are atomic accumulators starting at 0 (load-time zeroed);
// the finisher block re-zeroes them each run -> invariant across graph replays.
__device__ uint32_t g_Q[DIM * WORDS];          // 251 KB packed pos signs
__device__ int      g_TotPart[NCHUNK * DIM];   // deterministic Tot partials
__device__ int      g_A[BATCH * DIM];          // AND-popc accumulators (atomic)
__device__ int      g_C[BATCH];                // mask-popc accumulators (atomic)
__device__ int      g_FlagP = 0;               // pack-done counter
__device__ int      g_FlagM = 0;               // main-done counter

// ---------------------------------------------------------------------------
// Single fused kernel, ONE aliased shared buffer (fixes R12's 42 KB dual
// allocation -> back to full 840-block co-residency at 6 blocks/SM).
// Pack role (bid < NBP): pos tile -> transpose -> ballots -> g_Q -> arrive.
// Main role: x-ballot (overlaps pack DRAM) -> spin FlagP -> stage Q -> AND+popc
//   GEMM -> shared reduce -> one global atomicAdd per (b,d) -> arrive FlagM.
//   Last arriver = FINISHER: integer epilogue + sign + classify + state reset.
//
// Exactness: pos/level are exactly {-1,+1}; NUM_LEVELS=2 -> idx=round(x) with
// half-to-even so level-1 <=> x>0.5 strictly. All sums to `enc` are exact
// integers (int atomics associative -> deterministic, bit-exact).
// ---------------------------------------------------------------------------
__global__ void __launch_bounds__(320, 6)
fused_kernel(const float* __restrict__ x,
             const float* __restrict__ pos,
             const float* __restrict__ lvl,
             const float* __restrict__ cls,
             float* __restrict__ out) {
    __shared__ __align__(16) char smemBuf[BUF_BYTES];   // aliased by role/phase
    __shared__ int   sAcc[BPB][DIM];
    __shared__ int   sC[BPB];
    __shared__ int   sIsLast;
    __shared__ int   sTotF[DIM];
    __shared__ int   sCB[BATCH];

    const int tid  = threadIdx.x;
    const int lane = tid & 31;
    const int wid  = tid >> 5;                 // 10 warps

    if (blockIdx.x < NBP) {
        // ================= pack role =================
        float* tile = reinterpret_cast<float*>(smemBuf);         // PPB x 41
        const int p0 = blockIdx.x * PPB;
        const int p  = tid / DIM;
        const int d  = tid - p * DIM;
        const float* __restrict__ src = pos + (size_t)(p0 + p) * DIM + d;
        float* dst = &tile[p * 41 + d];
        #pragma unroll
        for (int k = 0; k < PPB / 8; k++)      // 16 coalesced loads/thread
            dst[k * (8 * 41)] = src[k * (8 * DIM)];
        __syncthreads();

        #pragma unroll
        for (int k = 0; k < 4; k++) {          // warp packs 4 dims x 4 words
            int dd = wid * 4 + k;
            unsigned q0 = __ballot_sync(0xffffffffu, tile[lane * 41 + dd]        > 0.0f);
            unsigned q1 = __ballot_sync(0xffffffffu, tile[(32 + lane) * 41 + dd] > 0.0f);
            unsigned q2 = __ballot_sync(0xffffffffu, tile[(64 + lane) * 41 + dd] > 0.0f);
            unsigned q3 = __ballot_sync(0xffffffffu, tile[(96 + lane) * 41 + dd] > 0.0f);
            if (lane == 0)                     // p0/32 multiple of 4 -> 16B-aligned
                *reinterpret_cast<uint4*>(&g_Q[dd * WORDS + (p0 >> 5)]) =
                    make_uint4(q0, q1, q2, q3);
        }
        __threadfence();
        __syncthreads();
        if (tid == 0) atomicAdd(&g_FlagP, 1);
    } else {
        // ================= main role =================
        uint32_t* sQ = reinterpret_cast<uint32_t*>(smemBuf);           // 9120 B
        uint32_t* sM = reinterpret_cast<uint32_t*>(smemBuf + SM_OFF);  // [BPB][CW]

        const int mb = blockIdx.x - NBP;
        const int c  = mb >> 4;                // chunk 0..27
        const int bq = mb & 15;
        const int b0 = bq * BPB;

        if (tid < DIM) {
            #pragma unroll
            for (int i = 0; i < BPB; i++) sAcc[i][tid] = 0;
        }
        if (tid < BPB) sC[tid] = 0;

        const int w0 = c * CW;
        int cc[BPB] = {0, 0, 0, 0};
        // Phase 1: x-ballot (no Q needed) — overlaps pack blocks' DRAM use.
        if (wid < 8) {
            const float* __restrict__ xb = x + (size_t)b0 * PIXELS + (size_t)w0 * 32;
            const int jbase = wid * (CW / 8);  // 7 words/warp
            #pragma unroll
            for (int jj = 0; jj < CW / 8; jj++) {
                int j = jbase + jj;
                #pragma unroll
                for (int i = 0; i < BPB; i++) {
                    float v = xb[(size_t)i * PIXELS + j * 32 + lane];
                    unsigned m = __ballot_sync(0xffffffffu, v > 0.5f);
                    cc[i] += __popc(m);
                    if (lane == 0) sM[i * CW + j] = m;
                }
            }
        }

        // Phase 2: wait for pack completion (pack blocks are wave-1, no deadlock).
        if (tid == 0) {
            volatile int* fp = &g_FlagP;
            while (*fp != NBP) { }
        }
        __syncthreads();

        // Phase 3: stage Q chunk (uint4).
        for (int i = tid; i < DIM * (CW / 4); i += 320) {
            int d = i / (CW / 4), j4 = i - d * (CW / 4);
            uint4 v = *reinterpret_cast<const uint4*>(&g_Q[d * WORDS + w0 + j4 * 4]);
            uint32_t* q = &sQ[d * QPITCH + j4 * 4];
            q[0] = v.x; q[1] = v.y; q[2] = v.z; q[3] = v.w;
        }
        __syncthreads();

        // Phase 4: AND+popc GEMM, per-lane dim accumulators -> shared reduce.
        if (wid < 8) {
            const int jbase = wid * (CW / 8);
            int aLo[BPB] = {0, 0, 0, 0};
            int aHi[BPB] = {0, 0, 0, 0};
            #pragma unroll
            for (int jj = 0; jj < CW / 8; jj++) {
                int j = jbase + jj;
                uint32_t q0 = sQ[lane * QPITCH + j];            // dim = lane
                #pragma unroll
                for (int i = 0; i < BPB; i++) aLo[i] += __popc(sM[i * CW + j] & q0);
                if (lane < 8) {
                    uint32_t q1 = sQ[(lane + 32) * QPITCH + j]; // dims 32..39
                    #pragma unroll
                    for (int i = 0; i < BPB; i++) aHi[i] += __popc(sM[i * CW + j] & q1);
                }
            }
            #pragma unroll
            for (int i = 0; i < BPB; i++) {
                atomicAdd(&sAcc[i][lane], aLo[i]);
                if (lane < 8) atomicAdd(&sAcc[i][lane + 32], aHi[i]);
                if (lane == 0) atomicAdd(&sC[i], cc[i]);
            }
            if (bq == 0) {                     // Tot partials from resident sQ
                #pragma unroll
                for (int k = 0; k < DIM / 8; k++) {
                    int d = wid + 8 * k;
                    int t = 0;
                    for (int j = lane; j < CW; j += 32)
                        t += __popc(sQ[d * QPITCH + j]);
                    t = __reduce_add_sync(0xffffffffu, t);
                    if (lane == 0) g_TotPart[c * DIM + d] = t;
                }
            }
        }
        __syncthreads();

        // One global atomicAdd per (b,d): 28 adds/address across all blocks.
        if (tid < DIM) {
            #pragma unroll
            for (int i = 0; i < BPB; i++)
                atomicAdd(&g_A[(b0 + i) * DIM + tid], sAcc[i][tid]);
        }
        if (tid < BPB) atomicAdd(&g_C[b0 + tid], sC[tid]);

        __threadfence();
        __syncthreads();
        if (tid == 0) {
            int done = atomicAdd(&g_FlagM, 1);
            sIsLast = (done == NMAIN - 1);
        }
        __syncthreads();

        // ================= finisher =================
        if (sIsLast) {
            float* encS = reinterpret_cast<float*>(smemBuf);   // aliases dead sQ/sM
            __threadfence();                   // acquire all main-block writes
            if (tid < DIM) {
                int t = 0;
                #pragma unroll
                for (int cc2 = 0; cc2 < NCHUNK; cc2++) t += g_TotPart[cc2 * DIM + tid];
                sTotF[tid] = t;
            }
            if (tid < BATCH) sCB[tid] = g_C[tid];
            __syncthreads();

            #pragma unroll
            for (int k = 0; k < (BATCH * DIM) / 320; k++) {   // 8 pairs/thread
                int p = k * 320 + tid;
                int b = p / DIM, d = p - b * DIM;
                int A   = 2 * g_A[p]    - sCB[b];
                int Tot = 2 * sTotF[d]  - PIXELS;
                float summed = lvl[d] * (float)(Tot - A) + lvl[DIM + d] * (float)A;
                encS[p] = (summed > 0.0f) ? 1.0f : -1.0f;
            }
            __syncthreads();

            #pragma unroll
            for (int k = 0; k < (BATCH * NUM_CLASSES) / 320; k++) {  // 2 outs/thread
                int t = k * 320 + tid;
                int b = t / NUM_CLASSES, cl = t - b * NUM_CLASSES;
                float acc = 0.0f;
                #pragma unroll
                for (int d = 0; d < DIM; d++) acc += encS[b * DIM + d] * cls[cl * DIM + d];
                out[t] = acc;
            }

            // Reset accumulators + flags for the next graph replay.
            #pragma unroll
            for (int k = 0; k < (BATCH * DIM) / 320; k++) g_A[k * 320 + tid] = 0;
            if (tid < BATCH) g_C[tid] = 0;
            if (tid == 0) { g_FlagP = 0; g_FlagM = 0; }
            __threadfence();
        }
    }
}

// ---------------------------------------------------------------------------
extern "C" void kernel_launch(void* const* d_in, const int* in_sizes, int n_in,
                              void* d_out, int out_size) {
    const float* x   = (const float*)d_in[0];   // [64, 224, 224]
    const float* pos = (const float*)d_in[1];   // [50176, 40]
    const float* lvl = (const float*)d_in[2];   // [2, 40]
    const float* cls = (const float*)d_in[3];   // [10, 40]
    float* out = (float*)d_out;                 // [64, 10]

    fused_kernel<<<NTOT, 320>>>(x, pos, lvl, cls, out);
}